// round 4
// baseline (speedup 1.0000x reference)
#include <cuda_runtime.h>
#include <cuda_fp16.h>
#include <cstdint>

// ---------------- problem constants ----------------
// x: (64,64,32,128) fp32 -> M = 131072 rows, K = 128
// out: (M,256) fp32 ; z = x @ [wo|wc] (N=512), out = sig(zo+bo)*tanh(sig(zc+bc))
// Grid: 2048 CTAs = 1024 M-tiles x 2 col-halves. CTA: 128 rows x 128 out cols.
static constexpr int THREADS = 256;

// ---------------- smem layout ----------------
static constexpr int OFF_BO   = 0;                    // 0.5*biaso slice, 128 fp32
static constexpr int OFF_BC   = 512;                  // 0.5*biasc slice, 128 fp32
static constexpr int SMEM_A0  = 1024;                 // A K-half 0: 128 rows x 128B
static constexpr int SMEM_A1  = SMEM_A0 + 16384;      // A K-half 1
static constexpr int SMEM_B0  = SMEM_A1 + 16384;      // B K-half 0: 256 rows x 128B
static constexpr int SMEM_B1  = SMEM_B0 + 32768;      // B K-half 1
static constexpr int SMEM_TOTAL = SMEM_B1 + 32768;    // 99328 B -> 2 CTAs/SM

// fp16 weights, [n (512 = gate-major: 0..255 = wo cols, 256..511 = wc cols)][k (128)]
__device__ __half g_W[512 * 128];

// ---------------- helpers ----------------
__device__ __forceinline__ uint32_t smem_u32(const void* p) {
    uint32_t a;
    asm("{ .reg .u64 t; cvta.to.shared.u64 t, %1; cvt.u32.u64 %0, t; }" : "=r"(a) : "l"(p));
    return a;
}
__device__ __forceinline__ float tanh_ap(float x) {
    float y; asm("tanh.approx.f32 %0, %1;" : "=f"(y) : "f"(x)); return y;
}
__device__ __forceinline__ uint32_t sw128(uint32_t off) {
    return off ^ ((off >> 3) & 0x70);
}
__device__ __forceinline__ void ldmx4(uint32_t a[4], uint32_t addr) {
    asm volatile("ldmatrix.sync.aligned.m8n8.x4.shared.b16 {%0,%1,%2,%3}, [%4];"
                 : "=r"(a[0]), "=r"(a[1]), "=r"(a[2]), "=r"(a[3]) : "r"(addr));
}
__device__ __forceinline__ void mma16816(float c[4], const uint32_t a[4],
                                         uint32_t b0, uint32_t b1) {
    asm volatile(
        "mma.sync.aligned.m16n8k16.row.col.f32.f16.f16.f32 "
        "{%0,%1,%2,%3}, {%4,%5,%6,%7}, {%8,%9}, {%0,%1,%2,%3};"
        : "+f"(c[0]), "+f"(c[1]), "+f"(c[2]), "+f"(c[3])
        : "r"(a[0]), "r"(a[1]), "r"(a[2]), "r"(a[3]), "r"(b0), "r"(b1));
}
// sigmoid(z+b) = 0.5*tanh(0.5*z + 0.5*b) + 0.5   (hb = 0.5*b precomputed)
__device__ __forceinline__ float sigf(float z, float hb) {
    return fmaf(tanh_ap(fmaf(z, 0.5f, hb)), 0.5f, 0.5f);
}

// ---------------- weight conversion: wo,wc fp32 -> g_W fp16 [n][k] ----------------
__global__ void convert_w_kernel(const float* __restrict__ wo, const float* __restrict__ wc) {
    int i = blockIdx.x * blockDim.x + threadIdx.x;   // 0 .. 65535
    int n = i >> 7;
    int k = i & 127;
    float v = (n < 256) ? wo[k * 256 + n] : wc[k * 256 + (n - 256)];
    g_W[i] = __float2half_rn(v);
}

// ---------------- main fused kernel ----------------
__global__ void __launch_bounds__(THREADS, 2)
mdlstm_main(const float* __restrict__ x,
            const float* __restrict__ biaso,
            const float* __restrict__ biasc,
            float* __restrict__ out) {
    extern __shared__ char smem[];
    const uint32_t sb = smem_u32(smem);
    const int tid = threadIdx.x;
    const int wid = tid >> 5;
    const int lid = tid & 31;

    const int row_base = (blockIdx.x >> 1) * 128;   // M tile
    const int cgCTA    = blockIdx.x & 1;            // which 128 output cols

    // ---- biases (half-scaled) for this CTA's 128 cols
    if (tid < 128) {
        reinterpret_cast<float*>(smem + OFF_BO)[tid] = 0.5f * biaso[cgCTA * 128 + tid];
    } else {
        int t = tid - 128;
        reinterpret_cast<float*>(smem + OFF_BC)[t] = 0.5f * biasc[cgCTA * 128 + t];
    }

    // ---- A: x tile fp32 -> fp16, SW128, two K-halves (rows of 64 halves = 128B)
    {
        const float4* xg = reinterpret_cast<const float4*>(x + (size_t)row_base * 128);
        #pragma unroll
        for (int it = 0; it < 16; ++it) {
            int i = tid + it * 256;            // 0..4095 float4s
            int r = i >> 5;                    // row 0..127
            int k = (i & 31) * 4;              // k 0..124
            float4 v = xg[i];
            __half2 h0 = __floats2half2_rn(v.x, v.y);
            __half2 h1 = __floats2half2_rn(v.z, v.w);
            uint32_t u0 = *reinterpret_cast<uint32_t*>(&h0);
            uint32_t u1 = *reinterpret_cast<uint32_t*>(&h1);
            unsigned long long pk = (static_cast<unsigned long long>(u1) << 32) | u0;
            int base = (k < 64) ? SMEM_A0 : SMEM_A1;
            uint32_t off = sw128((uint32_t)(r * 128 + (k & 63) * 2));
            *reinterpret_cast<unsigned long long*>(smem + base + off) = pk;
        }
    }

    // ---- B: 256 weight rows for this CTA (o-cols then c-cols), SW128, two K-halves
    {
        const uint4* wg = reinterpret_cast<const uint4*>(g_W);
        #pragma unroll
        for (int it = 0; it < 16; ++it) {
            int i = tid + it * 256;            // 0..4095 uint4s over [256][16]
            int nr = i >> 4;                   // 0..255 (smem row)
            int kq = (i & 15) * 8;             // k 0..120
            // global n: nr<128 -> o gate col cgCTA*128+nr ; else c gate (256 + ...)
            int ng = 128 + cgCTA * 128 + nr - ((nr < 128) ? 128 : 0);
            // equivalently: (nr<128) ? cgCTA*128+nr : 256 + cgCTA*128 + (nr-128)
            uint4 v = wg[ng * 16 + (i & 15)];
            int base = (kq < 64) ? SMEM_B0 : SMEM_B1;
            uint32_t off = sw128((uint32_t)(nr * 128 + (kq & 63) * 2));
            *reinterpret_cast<uint4*>(smem + base + off) = v;
        }
    }

    __syncthreads();

    // ---- warp layout: rg = wid>>1 (rows rg*32), cw = wid&1 (out cols cw*64 of this CTA)
    const int rg = wid >> 1;
    const int cw = wid & 1;

    // ---- preload A fragments for both m16 tiles, all 8 k-steps (reused 4x)
    uint32_t afr[2][8][4];
    #pragma unroll
    for (int mt = 0; mt < 2; ++mt) {
        int row = rg * 32 + mt * 16 + (lid & 15);
        #pragma unroll
        for (int ks = 0; ks < 8; ++ks) {
            int k8 = ks * 2 + (lid >> 4);
            uint32_t base = sb + ((k8 < 8) ? SMEM_A0 : SMEM_A1);
            ldmx4(afr[mt][ks], base + sw128((uint32_t)(row * 128 + (k8 & 7) * 16)));
        }
    }

    const float* hbo = reinterpret_cast<const float*>(smem + OFF_BO);
    const float* hbc = reinterpret_cast<const float*>(smem + OFF_BC);
    const int colq = (lid & 3) * 2;

    // ---- 4 chunks of 16 output cols; per chunk: 4 n8-tiles (2 o + 2 c) x 2 m-tiles
    #pragma unroll
    for (int ch = 0; ch < 4; ++ch) {
        const int cb = cw * 64 + ch * 16;     // local out-col base (0..112)

        float acc[2][4][4];
        #pragma unroll
        for (int mt = 0; mt < 2; ++mt)
            #pragma unroll
            for (int nt = 0; nt < 4; ++nt)
                #pragma unroll
                for (int r = 0; r < 4; ++r) acc[mt][nt][r] = 0.0f;

        #pragma unroll
        for (int ks4 = 0; ks4 < 4; ++ks4) {
            #pragma unroll
            for (int nt = 0; nt < 4; ++nt) {
                // nt 0,1 -> o tiles at smem rows cb, cb+8 ; nt 2,3 -> c tiles at 128+...
                int N = ((nt >> 1) ? 128 : 0) + cb + (nt & 1) * 8;
                int k8 = ks4 * 4 + (lid >> 3);
                uint32_t base = sb + ((k8 < 8) ? SMEM_B0 : SMEM_B1);
                uint32_t addr = base + sw128((uint32_t)((N + (lid & 7)) * 128 + (k8 & 7) * 16));
                uint32_t b[4];
                ldmx4(b, addr);            // b0,b1 = kstep 2*ks4 ; b2,b3 = kstep 2*ks4+1
                #pragma unroll
                for (int mt = 0; mt < 2; ++mt) {
                    mma16816(acc[mt][nt], afr[mt][2 * ks4],     b[0], b[1]);
                    mma16816(acc[mt][nt], afr[mt][2 * ks4 + 1], b[2], b[3]);
                }
            }
        }

        // ---- fused epilogue + store (quad-contiguous float2 -> 32B sectors)
        #pragma unroll
        for (int mt = 0; mt < 2; ++mt) {
            int row0 = row_base + rg * 32 + mt * 16 + (lid >> 2);
            #pragma unroll
            for (int j = 0; j < 2; ++j) {
                int col = cb + j * 8 + colq;               // local col
                float bo0 = hbo[col], bo1 = hbo[col + 1];
                float bc0 = hbc[col], bc1 = hbc[col + 1];
                const float* zo = acc[mt][j];
                const float* zc = acc[mt][2 + j];
                size_t gc = (size_t)cgCTA * 128 + col;

                // rows row0 (c0,c1)
                float v0 = sigf(zo[0], bo0) * tanh_ap(sigf(zc[0], bc0));
                float v1 = sigf(zo[1], bo1) * tanh_ap(sigf(zc[1], bc1));
                *reinterpret_cast<float2*>(out + (size_t)row0 * 256 + gc) =
                    make_float2(v0, v1);
                // rows row0+8 (c2,c3)
                float v2 = sigf(zo[2], bo0) * tanh_ap(sigf(zc[2], bc0));
                float v3 = sigf(zo[3], bo1) * tanh_ap(sigf(zc[3], bc1));
                *reinterpret_cast<float2*>(out + (size_t)(row0 + 8) * 256 + gc) =
                    make_float2(v2, v3);
            }
        }
    }
}

// ---------------- launch ----------------
extern "C" void kernel_launch(void* const* d_in, const int* in_sizes, int n_in,
                              void* d_out, int out_size) {
    const float* x  = (const float*)d_in[0];
    const float* wo = (const float*)d_in[7];
    const float* bo = (const float*)d_in[9];
    const float* wc = (const float*)d_in[10];
    const float* bc = (const float*)d_in[12];
    float* out = (float*)d_out;

    cudaFuncSetAttribute(mdlstm_main, cudaFuncAttributeMaxDynamicSharedMemorySize, SMEM_TOTAL);

    convert_w_kernel<<<256, 256>>>(wo, wc);
    mdlstm_main<<<2048, THREADS, SMEM_TOTAL>>>(x, bo, bc, out);
}

// round 5
// speedup vs baseline: 1.0500x; 1.0500x over previous
#include <cuda_runtime.h>
#include <cuda_fp16.h>
#include <cstdint>

// ---------------- problem constants ----------------
// x: (64,64,32,128) fp32 -> M = 131072 rows, K = 128
// out: (M,256) fp32 ; z = x @ [wo|wc] (N=512), out = sig(zo+bo)*tanh(sig(zc+bc))
// Grid: 2048 CTAs = 1024 M-tiles x 2 col-halves. CTA: 128 rows x 128 out cols.
static constexpr int THREADS = 256;

// ---------------- smem layout ----------------
static constexpr int OFF_BO   = 0;                    // 0.5*biaso slice, 128 fp32
static constexpr int OFF_BC   = 512;                  // 0.5*biasc slice, 128 fp32
static constexpr int SMEM_A0  = 1024;                 // A K-half 0: 128 rows x 128B
static constexpr int SMEM_A1  = SMEM_A0 + 16384;      // A K-half 1
static constexpr int SMEM_TOTAL = SMEM_A1 + 16384;    // 33792 B -> 2 CTAs/SM easily

// Weights in HMMA-fragment-linear order:
// frag f = ((cg*2 + cw)*4 + ch)*4*4 + ks4*4 + nt   (cg,cw in 0..1, ch,ks4,nt in 0..3)
// Each frag = 32 lanes x uint4 (4 u32 = q0..q3). Lane l, quad q holds half2:
//   n = gate_base + cg*128 + cw*64 + ch*16 + (nt&1)*8 + (l>>2)   (gate = nt>>1)
//   k = ks4*32 + (q&1)*8 + (q>>1)*16 + 2*(l&3)  (+0,+1 for the two halves)
__device__ uint4 g_Wf[256 * 32];

// ---------------- helpers ----------------
__device__ __forceinline__ uint32_t smem_u32(const void* p) {
    uint32_t a;
    asm("{ .reg .u64 t; cvta.to.shared.u64 t, %1; cvt.u32.u64 %0, t; }" : "=r"(a) : "l"(p));
    return a;
}
__device__ __forceinline__ float tanh_ap(float x) {
    float y; asm("tanh.approx.f32 %0, %1;" : "=f"(y) : "f"(x)); return y;
}
__device__ __forceinline__ uint32_t sw128(uint32_t off) {
    return off ^ ((off >> 3) & 0x70);
}
__device__ __forceinline__ void ldmx4(uint32_t a[4], uint32_t addr) {
    asm volatile("ldmatrix.sync.aligned.m8n8.x4.shared.b16 {%0,%1,%2,%3}, [%4];"
                 : "=r"(a[0]), "=r"(a[1]), "=r"(a[2]), "=r"(a[3]) : "r"(addr));
}
__device__ __forceinline__ void mma16816(float c[4], const uint32_t a[4],
                                         uint32_t b0, uint32_t b1) {
    asm volatile(
        "mma.sync.aligned.m16n8k16.row.col.f32.f16.f16.f32 "
        "{%0,%1,%2,%3}, {%4,%5,%6,%7}, {%8,%9}, {%0,%1,%2,%3};"
        : "+f"(c[0]), "+f"(c[1]), "+f"(c[2]), "+f"(c[3])
        : "r"(a[0]), "r"(a[1]), "r"(a[2]), "r"(a[3]), "r"(b0), "r"(b1));
}
// sigmoid(z+b) = 0.5*tanh(0.5*z + 0.5*b) + 0.5   (hb = 0.5*b precomputed)
__device__ __forceinline__ float sigf(float z, float hb) {
    return fmaf(tanh_ap(fmaf(z, 0.5f, hb)), 0.5f, 0.5f);
}

// ---------------- weight conversion: wo,wc fp32 -> fragment-linear fp16 ----------------
// One thread per (n,k) element; reads coalesced over n, scattered 2B store to frag slot.
__global__ void convert_w_kernel(const float* __restrict__ wo, const float* __restrict__ wc) {
    int t = blockIdx.x * blockDim.x + threadIdx.x;   // 0 .. 65535
    int k = t >> 9;          // 0..127
    int n = t & 511;         // 0..511 (0..255 = o gate, 256..511 = c gate)
    float v = (n < 256) ? wo[k * 256 + n] : wc[k * 256 + (n - 256)];

    int gate = n >> 8;                 // 0 = o, 1 = c
    int w    = n & 255;                // within-gate col
    int cg   = w >> 7;
    int loc  = w & 127;
    int cw   = loc >> 6;
    int ch   = (loc >> 4) & 3;
    int low  = loc & 15;
    int nt   = gate * 2 + (low >> 3);
    int lhi  = low & 7;                // = l >> 2

    int ks4  = k >> 5;
    int kr   = k & 31;
    int q    = kr >> 3;                // quad slot 0..3
    int llo  = (kr & 7) >> 1;          // = l & 3
    int l    = (lhi << 2) | llo;

    int f = (((cg * 2 + cw) * 4 + ch) * 16) + ks4 * 4 + nt;
    int half_idx = ((f * 32 + l) * 4 + q) * 2 + (k & 1);
    reinterpret_cast<__half*>(g_Wf)[half_idx] = __float2half_rn(v);
}

// ---------------- main fused kernel ----------------
__global__ void __launch_bounds__(THREADS, 2)
mdlstm_main(const float* __restrict__ x,
            const float* __restrict__ biaso,
            const float* __restrict__ biasc,
            float* __restrict__ out) {
    extern __shared__ char smem[];
    const uint32_t sb = smem_u32(smem);
    const int tid = threadIdx.x;
    const int wid = tid >> 5;
    const int lid = tid & 31;

    const int row_base = (blockIdx.x >> 1) * 128;   // M tile
    const int cgCTA    = blockIdx.x & 1;            // which 128 output cols

    // ---- biases (half-scaled) for this CTA's 128 cols
    if (tid < 128) {
        reinterpret_cast<float*>(smem + OFF_BO)[tid] = 0.5f * biaso[cgCTA * 128 + tid];
    } else {
        int t = tid - 128;
        reinterpret_cast<float*>(smem + OFF_BC)[t] = 0.5f * biasc[cgCTA * 128 + t];
    }

    // ---- A: x tile fp32 -> fp16, SW128, two K-halves (rows of 64 halves = 128B)
    {
        const float4* xg = reinterpret_cast<const float4*>(x + (size_t)row_base * 128);
        #pragma unroll
        for (int it = 0; it < 16; ++it) {
            int i = tid + it * 256;            // 0..4095 float4s
            int r = i >> 5;                    // row 0..127
            int k = (i & 31) * 4;              // k 0..124
            float4 v = xg[i];
            __half2 h0 = __floats2half2_rn(v.x, v.y);
            __half2 h1 = __floats2half2_rn(v.z, v.w);
            uint32_t u0 = *reinterpret_cast<uint32_t*>(&h0);
            uint32_t u1 = *reinterpret_cast<uint32_t*>(&h1);
            unsigned long long pk = (static_cast<unsigned long long>(u1) << 32) | u0;
            int base = (k < 64) ? SMEM_A0 : SMEM_A1;
            uint32_t off = sw128((uint32_t)(r * 128 + (k & 63) * 2));
            *reinterpret_cast<unsigned long long*>(smem + base + off) = pk;
        }
    }

    __syncthreads();

    // ---- warp layout: rg = wid>>1 (rows rg*32), cw = wid&1 (out cols cw*64 of this CTA)
    const int rg = wid >> 1;
    const int cw = wid & 1;

    // ---- preload A fragments for both m16 tiles, all 8 k-steps (reused 4x)
    uint32_t afr[2][8][4];
    #pragma unroll
    for (int mt = 0; mt < 2; ++mt) {
        int row = rg * 32 + mt * 16 + (lid & 15);
        #pragma unroll
        for (int ks = 0; ks < 8; ++ks) {
            int k8 = ks * 2 + (lid >> 4);
            uint32_t base = sb + ((k8 < 8) ? SMEM_A0 : SMEM_A1);
            ldmx4(afr[mt][ks], base + sw128((uint32_t)(row * 128 + (k8 & 7) * 16)));
        }
    }

    const float* hbo = reinterpret_cast<const float*>(smem + OFF_BO);
    const float* hbc = reinterpret_cast<const float*>(smem + OFF_BC);
    const int colq = (lid & 3) * 2;

    // B fragment base for this warp: frags [(cgCTA*2+cw)*64 + ch*16 + ks4*4 + nt]
    const uint4* wf_base = g_Wf + (size_t)((cgCTA * 2 + cw) * 64) * 32 + lid;

    // ---- 4 chunks of 16 output cols; per chunk: 4 n8-tiles (2 o + 2 c) x 2 m-tiles
    #pragma unroll
    for (int ch = 0; ch < 4; ++ch) {
        const int cb = cw * 64 + ch * 16;     // local out-col base (0..112)

        float acc[2][4][4];
        #pragma unroll
        for (int mt = 0; mt < 2; ++mt)
            #pragma unroll
            for (int nt = 0; nt < 4; ++nt)
                #pragma unroll
                for (int r = 0; r < 4; ++r) acc[mt][nt][r] = 0.0f;

        #pragma unroll
        for (int ks4 = 0; ks4 < 4; ++ks4) {
            // batch the 4 fragment loads (independent -> MLP=4)
            uint4 b0 = __ldg(wf_base + (ch * 16 + ks4 * 4 + 0) * 32);
            uint4 b1 = __ldg(wf_base + (ch * 16 + ks4 * 4 + 1) * 32);
            uint4 b2 = __ldg(wf_base + (ch * 16 + ks4 * 4 + 2) * 32);
            uint4 b3 = __ldg(wf_base + (ch * 16 + ks4 * 4 + 3) * 32);
            #pragma unroll
            for (int mt = 0; mt < 2; ++mt) {
                mma16816(acc[mt][0], afr[mt][2 * ks4],     b0.x, b0.y);
                mma16816(acc[mt][0], afr[mt][2 * ks4 + 1], b0.z, b0.w);
                mma16816(acc[mt][1], afr[mt][2 * ks4],     b1.x, b1.y);
                mma16816(acc[mt][1], afr[mt][2 * ks4 + 1], b1.z, b1.w);
                mma16816(acc[mt][2], afr[mt][2 * ks4],     b2.x, b2.y);
                mma16816(acc[mt][2], afr[mt][2 * ks4 + 1], b2.z, b2.w);
                mma16816(acc[mt][3], afr[mt][2 * ks4],     b3.x, b3.y);
                mma16816(acc[mt][3], afr[mt][2 * ks4 + 1], b3.z, b3.w);
            }
        }

        // ---- fused epilogue + store (quad-contiguous float2 -> 32B sectors)
        #pragma unroll
        for (int mt = 0; mt < 2; ++mt) {
            int row0 = row_base + rg * 32 + mt * 16 + (lid >> 2);
            #pragma unroll
            for (int j = 0; j < 2; ++j) {
                int col = cb + j * 8 + colq;               // local col
                float bo0 = hbo[col], bo1 = hbo[col + 1];
                float bc0 = hbc[col], bc1 = hbc[col + 1];
                const float* zo = acc[mt][j];
                const float* zc = acc[mt][2 + j];
                size_t gc = (size_t)cgCTA * 128 + col;

                // rows row0 (c0,c1)
                float v0 = sigf(zo[0], bo0) * tanh_ap(sigf(zc[0], bc0));
                float v1 = sigf(zo[1], bo1) * tanh_ap(sigf(zc[1], bc1));
                *reinterpret_cast<float2*>(out + (size_t)row0 * 256 + gc) =
                    make_float2(v0, v1);
                // rows row0+8 (c2,c3)
                float v2 = sigf(zo[2], bo0) * tanh_ap(sigf(zc[2], bc0));
                float v3 = sigf(zo[3], bo1) * tanh_ap(sigf(zc[3], bc1));
                *reinterpret_cast<float2*>(out + (size_t)(row0 + 8) * 256 + gc) =
                    make_float2(v2, v3);
            }
        }
    }
}

// ---------------- launch ----------------
extern "C" void kernel_launch(void* const* d_in, const int* in_sizes, int n_in,
                              void* d_out, int out_size) {
    const float* x  = (const float*)d_in[0];
    const float* wo = (const float*)d_in[7];
    const float* bo = (const float*)d_in[9];
    const float* wc = (const float*)d_in[10];
    const float* bc = (const float*)d_in[12];
    float* out = (float*)d_out;

    cudaFuncSetAttribute(mdlstm_main, cudaFuncAttributeMaxDynamicSharedMemorySize, SMEM_TOTAL);

    convert_w_kernel<<<256, 256>>>(wo, wc);
    mdlstm_main<<<2048, THREADS, SMEM_TOTAL>>>(x, bo, bc, out);
}